// round 2
// baseline (speedup 1.0000x reference)
#include <cuda_runtime.h>
#include <math.h>

// ---------------------------------------------------------------------------
// Problem constants
// ---------------------------------------------------------------------------
#define BB    8
#define CIN   128
#define COUT  128
#define KK3   3
#define KN    4
#define HH    160
#define WW    160
#define ATT   16
#define MID   32
#define HW    (HH*WW)          // 25600
#define IKK   (CIN*9)          // 1152
#define PB    (2*BB)           // 16 (path, batch) combos

// ---------------------------------------------------------------------------
// Scratch (static device globals; no runtime allocation)
// ---------------------------------------------------------------------------
__device__ float g_gap0[BB*CIN];
__device__ float g_gap1[BB*CIN];
__device__ float g_fdmean[BB*CIN];
__device__ float g_fdmax[BB*CIN];

__device__ float g_ca[PB*CIN];     // [p*8+b][cin]   input-channel attention
__device__ float g_fa[PB*COUT];    // [pb][cout]     filter attention
__device__ float g_sM[PB*9];       // [pb][kk]       sa * Mfd
__device__ float g_ka[PB*KN];      // [pb][n]        kernel softmax

__device__ float g_A[PB*COUT*IKK];    // fa-folded, ka-mixed weights  [pb][c][ikk]
__device__ float g_WfT[PB*IKK*COUT];  // final folded weights         [pb][ikk][o]

__device__ __forceinline__ float sigm(float x){ return 1.f/(1.f+expf(-x)); }

// ---------------------------------------------------------------------------
// Kernel 1: per-(b,c) plane reductions: mean(x0), mean(x1), max(x0-x1)
// ---------------------------------------------------------------------------
__global__ __launch_bounds__(256) void k_stats(const float* __restrict__ x0,
                                               const float* __restrict__ x1){
    int bc = blockIdx.x;                         // 0..1023
    const float4* p0 = (const float4*)(x0 + (size_t)bc*HW);
    const float4* p1 = (const float4*)(x1 + (size_t)bc*HW);
    float s0=0.f, s1=0.f, mx=-3.0e38f;
    for (int i = threadIdx.x; i < HW/4; i += 256){
        float4 a = p0[i], b = p1[i];
        s0 += (a.x+a.y)+(a.z+a.w);
        s1 += (b.x+b.y)+(b.z+b.w);
        float d0 = a.x-b.x, d1 = a.y-b.y, d2 = a.z-b.z, d3 = a.w-b.w;
        mx = fmaxf(mx, fmaxf(fmaxf(d0,d1), fmaxf(d2,d3)));
    }
    #pragma unroll
    for (int off=16; off; off>>=1){
        s0 += __shfl_down_sync(0xffffffffu, s0, off);
        s1 += __shfl_down_sync(0xffffffffu, s1, off);
        mx  = fmaxf(mx, __shfl_down_sync(0xffffffffu, mx, off));
    }
    __shared__ float r0[8], r1[8], rm[8];
    int w = threadIdx.x >> 5;
    if ((threadIdx.x & 31) == 0){ r0[w]=s0; r1[w]=s1; rm[w]=mx; }
    __syncthreads();
    if (threadIdx.x == 0){
        float S0=0.f, S1=0.f, M=-3.0e38f;
        #pragma unroll
        for (int i=0;i<8;++i){ S0+=r0[i]; S1+=r1[i]; M=fmaxf(M, rm[i]); }
        const float inv = 1.f/(float)HW;
        g_gap0[bc]   = S0*inv;
        g_gap1[bc]   = S1*inv;
        g_fdmean[bc] = (S0-S1)*inv;
        g_fdmax[bc]  = M;
    }
}

// ---------------------------------------------------------------------------
// Kernel 2: attention + dif_atten (one block per batch, 128 threads)
// ---------------------------------------------------------------------------
__global__ __launch_bounds__(128) void k_att(
    const float* __restrict__ fc_w,  const float* __restrict__ ln_g,  const float* __restrict__ ln_b,
    const float* __restrict__ ch_w,  const float* __restrict__ ch_b,
    const float* __restrict__ fl_w,  const float* __restrict__ fl_b,
    const float* __restrict__ sp_w,  const float* __restrict__ sp_b,
    const float* __restrict__ kn_w,  const float* __restrict__ kn_b,
    const float* __restrict__ mlp_w1,const float* __restrict__ mlp_b1,
    const float* __restrict__ mlp_w2,const float* __restrict__ mlp_b2)
{
    int b = blockIdx.x, tid = threadIdx.x;
    __shared__ float gA[128], gB[128], yv[ATT], hs[MID], mfd[9], kl[KN];

    // ---- Mfd (shared across both paths) ----
    gA[tid] = g_fdmean[b*CIN + tid];
    gB[tid] = g_fdmax [b*CIN + tid];
    __syncthreads();
    if (tid < MID){
        float sa_ = mlp_b1[tid], sm_ = mlp_b1[tid];
        for (int c=0;c<CIN;++c){ float w = mlp_w1[tid*CIN+c]; sa_ += w*gA[c]; sm_ += w*gB[c]; }
        hs[tid] = fmaxf(sa_,0.f) + fmaxf(sm_,0.f);
    }
    __syncthreads();
    if (tid < 9){
        float z = 2.f*mlp_b2[tid];
        for (int t=0;t<MID;++t) z += mlp_w2[tid*MID+t]*hs[t];
        mfd[tid] = sigm(z);
    }

    // ---- attention per path ----
    for (int p=0;p<2;++p){
        __syncthreads();
        gA[tid] = (p ? g_gap1 : g_gap0)[b*CIN + tid];
        __syncthreads();
        if (tid < ATT){
            float v = 0.f;
            for (int c=0;c<CIN;++c) v += fc_w[tid*CIN+c]*gA[c];
            yv[tid] = v;
        }
        __syncthreads();
        if (tid == 0){
            float mu = 0.f;
            for (int j=0;j<ATT;++j) mu += yv[j];
            mu *= (1.f/ATT);
            float var = 0.f;
            for (int j=0;j<ATT;++j){ float d = yv[j]-mu; var += d*d; }
            var *= (1.f/ATT);
            float inv = rsqrtf(var + 1e-5f);
            for (int j=0;j<ATT;++j)
                yv[j] = fmaxf(0.f, (yv[j]-mu)*inv*ln_g[j] + ln_b[j]);
        }
        __syncthreads();
        {
            float ac = ch_b[tid], af = fl_b[tid];
            for (int j=0;j<ATT;++j){ ac += ch_w[tid*ATT+j]*yv[j]; af += fl_w[tid*ATT+j]*yv[j]; }
            g_ca[(p*BB+b)*CIN  + tid] = sigm(ac);
            g_fa[(p*BB+b)*COUT + tid] = sigm(af);
        }
        if (tid < 9){
            float s = sp_b[tid];
            for (int j=0;j<ATT;++j) s += sp_w[tid*ATT+j]*yv[j];
            g_sM[(p*BB+b)*9 + tid] = sigm(s)*mfd[tid];
        }
        if (tid < KN){
            float l = kn_b[tid];
            for (int j=0;j<ATT;++j) l += kn_w[tid*ATT+j]*yv[j];
            kl[tid] = l;
        }
        __syncthreads();
        if (tid == 0){
            float m = fmaxf(fmaxf(kl[0],kl[1]), fmaxf(kl[2],kl[3]));
            float e0=expf(kl[0]-m), e1=expf(kl[1]-m), e2=expf(kl[2]-m), e3=expf(kl[3]-m);
            float s = e0+e1+e2+e3;
            g_ka[(p*BB+b)*KN+0] = e0/s; g_ka[(p*BB+b)*KN+1] = e1/s;
            g_ka[(p*BB+b)*KN+2] = e2/s; g_ka[(p*BB+b)*KN+3] = e3/s;
        }
    }
}

// ---------------------------------------------------------------------------
// Kernel 3a: A[pb][c][ikk] = fa[pb][c] * sum_n ka[pb][n]*weight[n][c][ikk]
// ---------------------------------------------------------------------------
__global__ __launch_bounds__(256) void k_agg(const float* __restrict__ weight){
    int pb  = blockIdx.y;
    int idx = blockIdx.x*256 + threadIdx.x;   // < 128*1152 = 147456
    int c   = idx / IKK;
    float k0 = g_ka[pb*KN+0], k1 = g_ka[pb*KN+1], k2 = g_ka[pb*KN+2], k3 = g_ka[pb*KN+3];
    const float* w = weight + idx;            // weight[(n*128+c)*1152+ikk] = weight[n*147456 + idx]
    float acc = k0*w[0] + k1*w[COUT*IKK] + k2*w[2*COUT*IKK] + k3*w[3*COUT*IKK];
    g_A[pb*(COUT*IKK) + idx] = acc * g_fa[pb*COUT + c];
}

// ---------------------------------------------------------------------------
// Kernel 3b: WfT[pb][ikk][o] = ca[i]*sM[kk] * sum_c fuse_w[o, p*128+c]*A[pb][c][ikk]
//   GEMM M=128(o) x N=64(ikk tile) x K=128(c);  grid (18 ntiles, 16 pb)
// ---------------------------------------------------------------------------
__global__ __launch_bounds__(256) void k_wf(const float* __restrict__ fuse_w){
    int pb = blockIdx.y, p = pb >> 3;
    int nt = blockIdx.x;
    int tid = threadIdx.x;
    int to = tid & 15;        // o-group: o = to*8 .. to*8+7
    int tn = tid >> 4;        // ikk-group: nn = tn*4 .. tn*4+3
    __shared__ __align__(16) float Fs[16][128];
    __shared__ __align__(16) float As[16][64];
    float acc[8][4];
    #pragma unroll
    for (int o=0;o<8;++o)
        #pragma unroll
        for (int n=0;n<4;++n) acc[o][n]=0.f;

    const float* Abase = g_A + (size_t)pb*(COUT*IKK);
    for (int ck=0; ck<8; ++ck){
        __syncthreads();
        #pragma unroll
        for (int j=0;j<8;++j){          // 2048 fuse elements
            int l = j*256 + tid; int o = l & 127, cc = l >> 7;
            Fs[cc][o] = fuse_w[o*(2*COUT) + p*COUT + ck*16 + cc];
        }
        #pragma unroll
        for (int j=0;j<4;++j){          // 1024 A elements
            int l = j*256 + tid; int nn = l & 63, cc = l >> 6;
            As[cc][nn] = Abase[(ck*16+cc)*IKK + nt*64 + nn];
        }
        __syncthreads();
        #pragma unroll
        for (int cc=0; cc<16; ++cc){
            float4 av = *(const float4*)&As[cc][tn*4];
            float a_[4] = {av.x, av.y, av.z, av.w};
            float4 f0 = *(const float4*)&Fs[cc][to*8];
            float4 f1 = *(const float4*)&Fs[cc][to*8+4];
            float f_[8] = {f0.x,f0.y,f0.z,f0.w, f1.x,f1.y,f1.z,f1.w};
            #pragma unroll
            for (int o=0;o<8;++o)
                #pragma unroll
                for (int n=0;n<4;++n)
                    acc[o][n] = fmaf(f_[o], a_[n], acc[o][n]);
        }
    }
    float* Wbase = g_WfT + (size_t)pb*(IKK*COUT);
    const float* cap = g_ca + pb*CIN;
    const float* sMp = g_sM + pb*9;
    #pragma unroll
    for (int n=0;n<4;++n){
        int ikk = nt*64 + tn*4 + n;
        int i = ikk/9, kk = ikk - i*9;
        float sc = cap[i]*sMp[kk];
        #pragma unroll
        for (int o=0;o<8;++o)
            Wbase[ikk*COUT + to*8 + o] = acc[o][n]*sc;
    }
}

// ---------------------------------------------------------------------------
// Kernel 4: direct 3x3 conv, both paths summed, folded weights, + fuse bias.
//   Block: 256 thr, tile = 64 out-ch x (8y x 16x), thread = 8 oc x 4 x.
//   Grid: (200 spatial tiles, 2 oc-tiles, 8 batches)
// ---------------------------------------------------------------------------
__global__ __launch_bounds__(256) void k_conv(const float* __restrict__ x0,
                                              const float* __restrict__ x1,
                                              const float* __restrict__ fuse_b,
                                              float* __restrict__ out){
    int b = blockIdx.z, octile = blockIdx.y;
    int tile = blockIdx.x;
    int txl = tile % 10, tyl = tile / 10;
    int xbase = txl*16, ybase = tyl*8;
    int tid = threadIdx.x;
    int q  = tid & 31, og = tid >> 5;
    int qy = q >> 2,  qx = q & 3;

    __shared__ __align__(16) float sInp[8][10][20];   // 8 ic, 10 rows, 18 used cols (stride 20)
    __shared__ __align__(16) float sW[8][9][64];      // 8 ic, 9 taps, 64 oc

    float acc[8][4];
    #pragma unroll
    for (int o=0;o<8;++o)
        #pragma unroll
        for (int j=0;j<4;++j) acc[o][j]=0.f;

    for (int p=0;p<2;++p){
        const float* xin = (p ? x1 : x0) + (size_t)b*CIN*HW;
        const float* Wb  = g_WfT + (size_t)(p*BB+b)*(IKK*COUT) + octile*64;
        for (int icc=0; icc<16; ++icc){
            __syncthreads();
            // weights: 4608 elements, coalesced (oc contiguous)
            #pragma unroll
            for (int j=0;j<18;++j){
                int l = j*256 + tid;
                int oc = l & 63, r = l >> 6;            // r = ic*9+kk, 0..71
                ((float*)sW)[l] = Wb[(icc*72 + r)*COUT + oc];
            }
            // input tile: 8 ic x 10 rows x 18 cols, zero-padded at borders
            #pragma unroll
            for (int j=0;j<6;++j){
                int l = j*256 + tid;
                if (l < 1440){
                    int col = l % 18; int rr = l / 18;
                    int row = rr % 10; int ic = rr / 10;
                    int gy = ybase - 1 + row, gx = xbase - 1 + col;
                    float v = 0.f;
                    if (gy >= 0 && gy < HH && gx >= 0 && gx < WW)
                        v = xin[(size_t)(icc*8+ic)*HW + gy*WW + gx];
                    sInp[ic][row][col] = v;
                }
            }
            __syncthreads();
            #pragma unroll 1
            for (int ic=0; ic<8; ++ic){
                #pragma unroll
                for (int ky=0; ky<3; ++ky){
                    float rv[6];
                    #pragma unroll
                    for (int j=0;j<6;++j) rv[j] = sInp[ic][qy+ky][qx*4 + j];
                    #pragma unroll
                    for (int kx=0; kx<3; ++kx){
                        float4 wa = *(const float4*)&sW[ic][ky*3+kx][og*8];
                        float4 wb = *(const float4*)&sW[ic][ky*3+kx][og*8+4];
                        float w_[8] = {wa.x,wa.y,wa.z,wa.w, wb.x,wb.y,wb.z,wb.w};
                        #pragma unroll
                        for (int o=0;o<8;++o)
                            #pragma unroll
                            for (int j=0;j<4;++j)
                                acc[o][j] = fmaf(w_[o], rv[kx+j], acc[o][j]);
                    }
                }
            }
        }
    }
    int yy = ybase + qy, xx = xbase + qx*4;
    #pragma unroll
    for (int o=0;o<8;++o){
        int oc = octile*64 + og*8 + o;
        float bias = fuse_b[oc];
        float4 v = make_float4(acc[o][0]+bias, acc[o][1]+bias,
                               acc[o][2]+bias, acc[o][3]+bias);
        *(float4*)&out[(((size_t)b*COUT + oc)*HH + yy)*WW + xx] = v;
    }
}

// ---------------------------------------------------------------------------
// Launch
// ---------------------------------------------------------------------------
extern "C" void kernel_launch(void* const* d_in, const int* in_sizes, int n_in,
                              void* d_out, int out_size){
    const float* x0     = (const float*)d_in[0];
    const float* x1     = (const float*)d_in[1];
    const float* fc_w   = (const float*)d_in[2];
    const float* ln_g   = (const float*)d_in[3];
    const float* ln_b   = (const float*)d_in[4];
    const float* ch_w   = (const float*)d_in[5];
    const float* ch_b   = (const float*)d_in[6];
    const float* fl_w   = (const float*)d_in[7];
    const float* fl_b   = (const float*)d_in[8];
    const float* sp_w   = (const float*)d_in[9];
    const float* sp_b   = (const float*)d_in[10];
    const float* kn_w   = (const float*)d_in[11];
    const float* kn_b   = (const float*)d_in[12];
    const float* weight = (const float*)d_in[13];
    const float* mlp_w1 = (const float*)d_in[14];
    const float* mlp_b1 = (const float*)d_in[15];
    const float* mlp_w2 = (const float*)d_in[16];
    const float* mlp_b2 = (const float*)d_in[17];
    const float* fuse_w = (const float*)d_in[18];
    const float* fuse_b = (const float*)d_in[19];
    float* out = (float*)d_out;

    k_stats<<<BB*CIN, 256>>>(x0, x1);
    k_att<<<BB, 128>>>(fc_w, ln_g, ln_b, ch_w, ch_b, fl_w, fl_b,
                       sp_w, sp_b, kn_w, kn_b, mlp_w1, mlp_b1, mlp_w2, mlp_b2);
    k_agg<<<dim3(576, PB), 256>>>(weight);
    k_wf <<<dim3(18, PB), 256>>>(fuse_w);
    k_conv<<<dim3(200, 2, BB), 256>>>(x0, x1, fuse_b, out);
}